// round 2
// baseline (speedup 1.0000x reference)
#include <cuda_runtime.h>

// Problem constants (fixed for this dataset entry)
#define TT 8192      // tokens = B*S = 4*2048
#define HH 2048      // hidden
#define EE 8         // experts
#define TOPK 2

#define BM 128
#define BN 128
#define BK 16

// ---------------- static scratch (no allocation allowed) ----------------
__device__ int   g_counts[EE];
__device__ int   g_list[EE][TT];          // compacted slot ids per expert (slot = 2*t + k)
__device__ float g_gate[2 * TT];          // gate value per slot
__device__ float g_Y[(size_t)2 * TT * HH];// per-slot expert outputs (gate*(xW+b)), 128 MB

// ---------------- packed f32x2 helpers ----------------
__device__ __forceinline__ unsigned long long pack2(float lo, float hi) {
    unsigned long long r;
    asm("mov.b64 %0, {%1, %2};" : "=l"(r) : "f"(lo), "f"(hi));
    return r;
}
__device__ __forceinline__ void unpack2(unsigned long long v, float& lo, float& hi) {
    asm("mov.b64 {%0, %1}, %2;" : "=f"(lo), "=f"(hi) : "l"(v));
}
__device__ __forceinline__ void ffma2(unsigned long long& c, unsigned long long a, unsigned long long b) {
    asm("fma.rn.f32x2 %0, %1, %2, %0;" : "+l"(c) : "l"(a), "l"(b));
}

// ---------------- kernel 0: reset routing counters ----------------
__global__ void k_init() {
    if (threadIdx.x < EE) g_counts[threadIdx.x] = 0;
}

// ---------------- kernel 1: gating (one warp per token) ----------------
__global__ void k_gate(const float* __restrict__ x,
                       const float* __restrict__ Wg,
                       const float* __restrict__ bg) {
    int gw = (blockIdx.x * blockDim.x + threadIdx.x) >> 5;
    int lane = threadIdx.x & 31;
    if (gw >= TT) return;
    const float* xr = x + (size_t)gw * HH;

    float acc[EE];
#pragma unroll
    for (int e = 0; e < EE; ++e) acc[e] = 0.0f;

    for (int h = lane; h < HH; h += 32) {
        float xv = xr[h];
        const float4* w4 = (const float4*)(Wg + (size_t)h * EE);
        float4 w0 = w4[0];
        float4 w1 = w4[1];
        acc[0] += xv * w0.x; acc[1] += xv * w0.y;
        acc[2] += xv * w0.z; acc[3] += xv * w0.w;
        acc[4] += xv * w1.x; acc[5] += xv * w1.y;
        acc[6] += xv * w1.z; acc[7] += xv * w1.w;
    }
#pragma unroll
    for (int o = 16; o; o >>= 1) {
#pragma unroll
        for (int e = 0; e < EE; ++e)
            acc[e] += __shfl_xor_sync(0xffffffffu, acc[e], o);
    }
    if (lane == 0) {
        float m = -1e30f;
#pragma unroll
        for (int e = 0; e < EE; ++e) {
            acc[e] += bg[e];
            m = fmaxf(m, acc[e]);
        }
        float sc[EE];
        float s = 0.0f;
#pragma unroll
        for (int e = 0; e < EE; ++e) { sc[e] = expf(acc[e] - m); s += sc[e]; }
        float inv = 1.0f / s;
#pragma unroll
        for (int e = 0; e < EE; ++e) sc[e] *= inv;

        // top-2 (ties -> lowest index, matching lax.top_k)
        int e0 = 0;
#pragma unroll
        for (int e = 1; e < EE; ++e) if (sc[e] > sc[e0]) e0 = e;
        int e1 = (e0 == 0) ? 1 : 0;
#pragma unroll
        for (int e = 0; e < EE; ++e)
            if (e != e0 && sc[e] > sc[e1]) e1 = e;

        int t = gw;
        g_gate[2 * t + 0] = sc[e0];
        g_gate[2 * t + 1] = sc[e1];
        int p0 = atomicAdd(&g_counts[e0], 1);
        g_list[e0][p0] = 2 * t + 0;
        int p1 = atomicAdd(&g_counts[e1], 1);
        g_list[e1][p1] = 2 * t + 1;
    }
}

// ---------------- kernel 2: grouped (gathered) SGEMM per expert ----------------
// Y[slot, :] = gate(slot) * ( x[token(slot), :] @ We[e] + be[e] )
__global__ __launch_bounds__(256, 2)
void k_gemm(const float* __restrict__ x,
            const float* __restrict__ We,
            const float* __restrict__ be) {
    const int e = blockIdx.z;
    const int count = g_counts[e];
    const int row0 = blockIdx.y * BM;
    if (row0 >= count) return;
    const int n0 = blockIdx.x * BN;

    __shared__ __align__(16) float  As[BK][BM + 4];
    __shared__ __align__(16) float4 Bs4[BK][BN / 4];

    const int tid = threadIdx.x;
    const float* Wb = We + (size_t)e * HH * HH;

    // A-load assignment: 512 float4 (128 rows x 4 chunks of 4 k-elems), 2 per thread
    const int akq = (tid & 3) * 4;     // k offset within tile
    int arow[2];
    const float* aptr[2];
#pragma unroll
    for (int it = 0; it < 2; ++it) {
        int i = tid + it * 256;
        int r = i >> 2;                // 0..127
        arow[it] = r;
        int gr = row0 + r;
        if (gr < count) {
            int slot = g_list[e][gr];
            aptr[it] = x + (size_t)(slot >> 1) * HH;
        } else {
            aptr[it] = 0;
        }
    }

    unsigned long long c[8][4];
#pragma unroll
    for (int i = 0; i < 8; ++i)
#pragma unroll
        for (int j = 0; j < 4; ++j) c[i][j] = 0ull;

    const int tm = (tid >> 4) << 3;    // output row base within tile
    const int tn = (tid & 15) << 3;    // output col base within tile

    for (int k0 = 0; k0 < HH; k0 += BK) {
        // load A (gathered rows), store transposed As[k][m]
#pragma unroll
        for (int it = 0; it < 2; ++it) {
            float4 v = make_float4(0.f, 0.f, 0.f, 0.f);
            if (aptr[it]) v = *(const float4*)(aptr[it] + k0 + akq);
            int r = arow[it];
            As[akq + 0][r] = v.x;
            As[akq + 1][r] = v.y;
            As[akq + 2][r] = v.z;
            As[akq + 3][r] = v.w;
        }
        // load B tile [BK][BN]
#pragma unroll
        for (int it = 0; it < 2; ++it) {
            int i = tid + it * 256;    // 0..511
            int k = i >> 5;            // 0..15
            int n4 = i & 31;           // 0..31
            Bs4[k][n4] = *(const float4*)(Wb + (size_t)(k0 + k) * HH + n0 + n4 * 4);
        }
        __syncthreads();

#pragma unroll
        for (int kk = 0; kk < BK; ++kk) {
            float4 a0 = *(const float4*)&As[kk][tm];
            float4 a1 = *(const float4*)&As[kk][tm + 4];
            float4 b0 = Bs4[kk][tn >> 2];
            float4 b1 = Bs4[kk][(tn >> 2) + 1];
            unsigned long long bb[4];
            bb[0] = pack2(b0.x, b0.y);
            bb[1] = pack2(b0.z, b0.w);
            bb[2] = pack2(b1.x, b1.y);
            bb[3] = pack2(b1.z, b1.w);
            float av[8] = {a0.x, a0.y, a0.z, a0.w, a1.x, a1.y, a1.z, a1.w};
#pragma unroll
            for (int i = 0; i < 8; ++i) {
                unsigned long long aa = pack2(av[i], av[i]);
#pragma unroll
                for (int j = 0; j < 4; ++j) ffma2(c[i][j], aa, bb[j]);
            }
        }
        __syncthreads();
    }

    // epilogue: Y[slot] = gate * (acc + bias)
    float bias[8];
    const float* bptr = be + (size_t)e * HH + n0 + tn;
#pragma unroll
    for (int j = 0; j < 8; ++j) bias[j] = bptr[j];

#pragma unroll
    for (int i = 0; i < 8; ++i) {
        int gr = row0 + tm + i;
        if (gr < count) {
            int slot = g_list[e][gr];
            float gate = g_gate[slot];
            float* yr = g_Y + (size_t)slot * HH + n0 + tn;
            float v[8];
#pragma unroll
            for (int j = 0; j < 4; ++j) {
                float lo, hi;
                unpack2(c[i][j], lo, hi);
                v[2 * j]     = gate * (lo + bias[2 * j]);
                v[2 * j + 1] = gate * (hi + bias[2 * j + 1]);
            }
            ((float4*)yr)[0] = make_float4(v[0], v[1], v[2], v[3]);
            ((float4*)yr)[1] = make_float4(v[4], v[5], v[6], v[7]);
        }
    }
}

// ---------------- kernel 3: combine (fixed k=0 then k=1 order -> deterministic) --------
__global__ void k_combine(float* __restrict__ out) {
    size_t i = (size_t)blockIdx.x * blockDim.x + threadIdx.x;   // float4 index
    const size_t H4 = HH / 4;
    size_t t = i / H4;
    size_t h4 = i - t * H4;
    const float4* Y4 = (const float4*)g_Y;
    float4 a = Y4[(2 * t) * H4 + h4];
    float4 b = Y4[(2 * t + 1) * H4 + h4];
    float4 r;
    r.x = a.x + b.x; r.y = a.y + b.y; r.z = a.z + b.z; r.w = a.w + b.w;
    ((float4*)out)[i] = r;
}

// ---------------- launch ----------------
extern "C" void kernel_launch(void* const* d_in, const int* in_sizes, int n_in,
                              void* d_out, int out_size) {
    const float* x  = (const float*)d_in[0];
    const float* Wg = (const float*)d_in[1];
    const float* bg = (const float*)d_in[2];
    const float* We = (const float*)d_in[3];
    const float* be = (const float*)d_in[4];
    float* out = (float*)d_out;

    k_init<<<1, 32>>>();
    k_gate<<<TT / 8, 256>>>(x, Wg, bg);
    dim3 grid(HH / BN, TT / BM, EE);
    k_gemm<<<grid, 256>>>(x, We, be);
    k_combine<<<(TT * (HH / 4)) / 256, 256>>>(out);
}

// round 5
// speedup vs baseline: 2.6776x; 2.6776x over previous
#include <cuda_runtime.h>
#include <cuda_bf16.h>
#include <cstdint>

// Problem constants
#define TT 8192
#define HH 2048
#define EE 8

// GEMM config
#define BM 128
#define BN 128
#define BK 64
#define NCH (HH / BK)          // 32 k-chunks
#define STG 3
#define MAT_BYTES 16384        // 128 rows x 128B
#define STAGE_BYTES (4 * MAT_BYTES)
#define SMEM_NEED (STG * STAGE_BYTES)   // 196608

// ---------------- static scratch ----------------
__device__ int   g_counts[EE];
__device__ int   g_list[EE][TT];
__device__ float g_gate[2 * TT];
__device__ float g_Y[(size_t)2 * TT * HH];
__device__ __nv_bfloat16 g_Ah[(size_t)TT * HH];
__device__ __nv_bfloat16 g_Al[(size_t)TT * HH];
__device__ __nv_bfloat16 g_Bh[(size_t)EE * HH * HH];   // [e][n][k]
__device__ __nv_bfloat16 g_Bl[(size_t)EE * HH * HH];

// ---------------- helpers ----------------
__device__ __forceinline__ uint32_t smem_u32(const void* p) {
    uint32_t a;
    asm("{ .reg .u64 t; cvta.to.shared.u64 t, %1; cvt.u32.u64 %0, t; }" : "=r"(a) : "l"(p));
    return a;
}
// pack: low half <- flo, high half <- fhi
__device__ __forceinline__ uint32_t bf2(float flo, float fhi) {
    uint32_t r;
    asm("cvt.rn.bf16x2.f32 %0, %1, %2;" : "=r"(r) : "f"(fhi), "f"(flo));
    return r;
}

#define CPA(dst, src) \
    asm volatile("cp.async.cg.shared.global [%0], [%1], 16;" :: "r"(dst), "l"(src))
#define CP_COMMIT() asm volatile("cp.async.commit_group;" ::: "memory")
#define CP_WAIT1()  asm volatile("cp.async.wait_group 1;" ::: "memory")

#define LDSM4(r, addr) \
    asm volatile("ldmatrix.sync.aligned.m8n8.x4.shared.b16 {%0,%1,%2,%3}, [%4];" \
                 : "=r"((r)[0]), "=r"((r)[1]), "=r"((r)[2]), "=r"((r)[3]) : "r"(addr))

#define MMA(c, a, b) \
    asm volatile("mma.sync.aligned.m16n8k16.row.col.f32.bf16.bf16.f32 " \
                 "{%0,%1,%2,%3},{%4,%5,%6,%7},{%8,%9},{%0,%1,%2,%3};" \
                 : "+f"((c)[0]), "+f"((c)[1]), "+f"((c)[2]), "+f"((c)[3]) \
                 : "r"((a)[0]), "r"((a)[1]), "r"((a)[2]), "r"((a)[3]), \
                   "r"((b)[0]), "r"((b)[1]))

// ---------------- kernel 0: reset counters ----------------
__global__ void k_init() {
    if (threadIdx.x < EE) g_counts[threadIdx.x] = 0;
}

// ---------------- kernel 1: x -> bf16 hi/lo ----------------
__global__ void k_prep_x(const float* __restrict__ x) {
    size_t idx = (size_t)blockIdx.x * blockDim.x + threadIdx.x;  // float4 index
    float4 v = ((const float4*)x)[idx];
    uint32_t h0 = bf2(v.x, v.y);
    uint32_t h1 = bf2(v.z, v.w);
    float lx = v.x - __uint_as_float(h0 << 16);
    float ly = v.y - __uint_as_float(h0 & 0xffff0000u);
    float lz = v.z - __uint_as_float(h1 << 16);
    float lw = v.w - __uint_as_float(h1 & 0xffff0000u);
    ((uint2*)g_Ah)[idx] = make_uint2(h0, h1);
    ((uint2*)g_Al)[idx] = make_uint2(bf2(lx, ly), bf2(lz, lw));
}

// ---------------- kernel 2: We [e][k][n] -> Bh/Bl [e][n][k] (transpose+split) ----
__global__ void k_prep_B(const float* __restrict__ We) {
    const int e = blockIdx.z;
    const int k0 = blockIdx.y * 64;
    const int n0 = blockIdx.x * 64;
    __shared__ float t[64][65];
    const int tid = threadIdx.x;
#pragma unroll
    for (int q = 0; q < 16; ++q) {
        int lin = q * 256 + tid;
        int kr = lin >> 6, nc = lin & 63;
        t[kr][nc] = We[((size_t)e * HH + (k0 + kr)) * HH + n0 + nc];
    }
    __syncthreads();
#pragma unroll
    for (int q = 0; q < 8; ++q) {
        int lin = q * 256 + tid;
        int nr = lin >> 5, kc = (lin & 31) * 2;
        float a = t[kc][nr], b = t[kc + 1][nr];
        uint32_t h = bf2(a, b);
        float la = a - __uint_as_float(h << 16);
        float lb = b - __uint_as_float(h & 0xffff0000u);
        uint32_t l = bf2(la, lb);
        size_t off = ((size_t)e * HH + (n0 + nr)) * HH + k0 + kc;
        *(uint32_t*)(g_Bh + off) = h;
        *(uint32_t*)(g_Bl + off) = l;
    }
}

// ---------------- kernel 3: gating (one warp per token) ----------------
__global__ void k_gate(const float* __restrict__ x,
                       const float* __restrict__ Wg,
                       const float* __restrict__ bg) {
    int gw = (blockIdx.x * blockDim.x + threadIdx.x) >> 5;
    int lane = threadIdx.x & 31;
    if (gw >= TT) return;
    const float* xr = x + (size_t)gw * HH;
    float acc[EE];
#pragma unroll
    for (int e = 0; e < EE; ++e) acc[e] = 0.0f;
    for (int h = lane; h < HH; h += 32) {
        float xv = xr[h];
        const float4* w4 = (const float4*)(Wg + (size_t)h * EE);
        float4 w0 = w4[0], w1 = w4[1];
        acc[0] += xv * w0.x; acc[1] += xv * w0.y;
        acc[2] += xv * w0.z; acc[3] += xv * w0.w;
        acc[4] += xv * w1.x; acc[5] += xv * w1.y;
        acc[6] += xv * w1.z; acc[7] += xv * w1.w;
    }
#pragma unroll
    for (int o = 16; o; o >>= 1)
#pragma unroll
        for (int e = 0; e < EE; ++e)
            acc[e] += __shfl_xor_sync(0xffffffffu, acc[e], o);
    if (lane == 0) {
        float m = -1e30f;
#pragma unroll
        for (int e = 0; e < EE; ++e) { acc[e] += bg[e]; m = fmaxf(m, acc[e]); }
        float sc[EE], s = 0.0f;
#pragma unroll
        for (int e = 0; e < EE; ++e) { sc[e] = expf(acc[e] - m); s += sc[e]; }
        float inv = 1.0f / s;
#pragma unroll
        for (int e = 0; e < EE; ++e) sc[e] *= inv;
        int e0 = 0;
#pragma unroll
        for (int e = 1; e < EE; ++e) if (sc[e] > sc[e0]) e0 = e;
        int e1 = (e0 == 0) ? 1 : 0;
#pragma unroll
        for (int e = 0; e < EE; ++e) if (e != e0 && sc[e] > sc[e1]) e1 = e;
        int t = gw;
        g_gate[2 * t + 0] = sc[e0];
        g_gate[2 * t + 1] = sc[e1];
        int p0 = atomicAdd(&g_counts[e0], 1);
        g_list[e0][p0] = 2 * t + 0;
        int p1 = atomicAdd(&g_counts[e1], 1);
        g_list[e1][p1] = 2 * t + 1;
    }
}

// ---------------- kernel 4: split-bf16 grouped GEMM on HMMA ----------------
__global__ __launch_bounds__(256, 1)
void k_gemm_mma(const float* __restrict__ be) {
    const int e = blockIdx.z;
    const int count = g_counts[e];
    const int row0 = blockIdx.y * BM;
    if (row0 >= count) return;
    const int n0 = blockIdx.x * BN;

    extern __shared__ char smem_raw[];
    const uint32_t sb = smem_u32(smem_raw);
    const int tid = threadIdx.x;
    const int w = tid >> 5, l = tid & 31;

    // ---- cp.async assignments: 4 granules (rows rA+32q, 16B chunk ch) per matrix ----
    const int rA = tid >> 3;
    const int ch = tid & 7;
    const __nv_bfloat16* srcAh[4];
    const __nv_bfloat16* srcAl[4];
    const __nv_bfloat16* srcBh[4];
    const __nv_bfloat16* srcBl[4];
    uint32_t dstoff[4];
#pragma unroll
    for (int q = 0; q < 4; ++q) {
        int r = rA + 32 * q;
        int gr = row0 + r;
        int cl = (gr < count) ? gr : (count - 1);
        int slot = g_list[e][cl];
        size_t abase = (size_t)(slot >> 1) * HH + ch * 8;
        srcAh[q] = g_Ah + abase;
        srcAl[q] = g_Al + abase;
        size_t bbase = ((size_t)e * HH + n0 + r) * HH + ch * 8;
        srcBh[q] = g_Bh + bbase;
        srcBl[q] = g_Bl + bbase;
        dstoff[q] = (uint32_t)r * 128u + (uint32_t)((ch ^ (rA & 7)) << 4);
    }

    auto issue = [&](int s, int c) {
        const uint32_t base = sb + s * STAGE_BYTES;
        const int ke = c * BK;   // element k offset
#pragma unroll
        for (int q = 0; q < 4; ++q) CPA(base + dstoff[q], srcAh[q] + ke);
#pragma unroll
        for (int q = 0; q < 4; ++q) CPA(base + MAT_BYTES + dstoff[q], srcAl[q] + ke);
#pragma unroll
        for (int q = 0; q < 4; ++q) CPA(base + 2 * MAT_BYTES + dstoff[q], srcBh[q] + ke);
#pragma unroll
        for (int q = 0; q < 4; ++q) CPA(base + 3 * MAT_BYTES + dstoff[q], srcBl[q] + ke);
    };

    // prologue: stages 0,1
    issue(0, 0); CP_COMMIT();
    issue(1, 1); CP_COMMIT();

    // ---- per-warp tile: m_base 64-row half, n_base 32-col quarter ----
    const int m_base = (w & 1) * 64;
    const int n_base = (w >> 1) * 32;

    uint32_t rowA[4], rowB[2], xoA[4], xoB[4];
#pragma unroll
    for (int i = 0; i < 4; ++i) rowA[i] = (uint32_t)(m_base + 16 * i + (l & 15)) * 128u;
#pragma unroll
    for (int j2 = 0; j2 < 2; ++j2)
        rowB[j2] = (uint32_t)(n_base + 16 * j2 + (l & 7) + ((l >> 4) << 3)) * 128u;
#pragma unroll
    for (int ks = 0; ks < 4; ++ks) {
        xoA[ks] = (uint32_t)(((ks * 2 + (l >> 4)) ^ (l & 7)) << 4);
        xoB[ks] = (uint32_t)(((ks * 2 + ((l >> 3) & 1)) ^ (l & 7)) << 4);
    }

    float acc[4][4][4];
#pragma unroll
    for (int i = 0; i < 4; ++i)
#pragma unroll
        for (int j = 0; j < 4; ++j)
#pragma unroll
            for (int q = 0; q < 4; ++q) acc[i][j][q] = 0.0f;

    for (int c = 0; c < NCH; ++c) {
        CP_WAIT1();
        __syncthreads();
        if (c + 2 < NCH) issue((c + 2) % STG, c + 2);
        CP_COMMIT();   // empty group near the tail keeps wait_group(1) semantics correct

        const uint32_t Ah = sb + (c % STG) * STAGE_BYTES;
        const uint32_t Al = Ah + MAT_BYTES;
        const uint32_t Bh = Ah + 2 * MAT_BYTES;
        const uint32_t Bl = Ah + 3 * MAT_BYTES;

#pragma unroll
        for (int ks = 0; ks < 4; ++ks) {
            uint32_t fah[4][4], fal[4][4], fbh[2][4], fbl[2][4];
#pragma unroll
            for (int i = 0; i < 4; ++i) {
                LDSM4(fah[i], Ah + rowA[i] + xoA[ks]);
                LDSM4(fal[i], Al + rowA[i] + xoA[ks]);
            }
#pragma unroll
            for (int j2 = 0; j2 < 2; ++j2) {
                LDSM4(fbh[j2], Bh + rowB[j2] + xoB[ks]);
                LDSM4(fbl[j2], Bl + rowB[j2] + xoB[ks]);
            }
#pragma unroll
            for (int i = 0; i < 4; ++i) {
#pragma unroll
                for (int j = 0; j < 4; ++j) {
                    uint32_t* bh = &fbh[j >> 1][(j & 1) * 2];
                    uint32_t* bl = &fbl[j >> 1][(j & 1) * 2];
                    MMA(acc[i][j], fah[i], bh);
                    MMA(acc[i][j], fah[i], bl);
                    MMA(acc[i][j], fal[i], bh);
                }
            }
        }
    }

    // ---- epilogue: Y[slot] = gate * (acc + be) ----
    float2 bias[4];
#pragma unroll
    for (int j = 0; j < 4; ++j) {
        int col = n_base + 8 * j + 2 * (l & 3);
        bias[j] = *(const float2*)(be + (size_t)e * HH + n0 + col);
    }
#pragma unroll
    for (int i = 0; i < 4; ++i) {
#pragma unroll
        for (int half = 0; half < 2; ++half) {
            int r = m_base + 16 * i + (l >> 2) + 8 * half;
            int gr = row0 + r;
            if (gr < count) {
                int slot = g_list[e][gr];
                float gate = g_gate[slot];
                float* yr = g_Y + (size_t)slot * HH + n0;
#pragma unroll
                for (int j = 0; j < 4; ++j) {
                    int col = n_base + 8 * j + 2 * (l & 3);
                    float2 o;
                    o.x = gate * (acc[i][j][half * 2 + 0] + bias[j].x);
                    o.y = gate * (acc[i][j][half * 2 + 1] + bias[j].y);
                    *(float2*)(yr + col) = o;
                }
            }
        }
    }
}

// ---------------- kernel 5: combine ----------------
__global__ void k_combine(float* __restrict__ out) {
    size_t i = (size_t)blockIdx.x * blockDim.x + threadIdx.x;
    const size_t H4 = HH / 4;
    size_t t = i / H4;
    size_t h4 = i - t * H4;
    const float4* Y4 = (const float4*)g_Y;
    float4 a = Y4[(2 * t) * H4 + h4];
    float4 b = Y4[(2 * t + 1) * H4 + h4];
    ((float4*)out)[i] = make_float4(a.x + b.x, a.y + b.y, a.z + b.z, a.w + b.w);
}

// ---------------- launch ----------------
extern "C" void kernel_launch(void* const* d_in, const int* in_sizes, int n_in,
                              void* d_out, int out_size) {
    const float* x  = (const float*)d_in[0];
    const float* Wg = (const float*)d_in[1];
    const float* bg = (const float*)d_in[2];
    const float* We = (const float*)d_in[3];
    const float* be = (const float*)d_in[4];
    float* out = (float*)d_out;

    cudaFuncSetAttribute(k_gemm_mma, cudaFuncAttributeMaxDynamicSharedMemorySize, SMEM_NEED);

    k_init<<<1, 32>>>();
    k_prep_x<<<(TT * HH / 4) / 256, 256>>>(x);
    k_prep_B<<<dim3(HH / 64, HH / 64, EE), 256>>>(We);
    k_gate<<<TT / 8, 256>>>(x, Wg, bg);
    k_gemm_mma<<<dim3(HH / BN, TT / BM, EE), 256, SMEM_NEED>>>(be);
    k_combine<<<(TT * (HH / 4)) / 256, 256>>>(out);
}

// round 7
// speedup vs baseline: 3.2251x; 1.2045x over previous
#include <cuda_runtime.h>
#include <cuda_fp16.h>
#include <cstdint>

// Problem constants
#define TT 8192
#define HH 2048
#define EE 8

// GEMM config
#define BM 128
#define BN 128
#define BK 64
#define NCH (HH / BK)          // 32 k-chunks
#define STG 4
#define MAT_BYTES 16384        // 128 rows x 128B (64 fp16)
#define STAGE_BYTES (3 * MAT_BYTES)       // Ah, Bh, Bl
#define SMEM_NEED (STG * STAGE_BYTES)     // 196608
#define BSCALE 4096.0f
#define INV_BSCALE (1.0f / 4096.0f)

// ---------------- static scratch ----------------
__device__ int    g_counts[EE];
__device__ int    g_list[EE][TT];
__device__ float  g_gate[2 * TT];
__device__ float  g_Y[(size_t)2 * TT * HH];
__device__ __half g_Ah[(size_t)TT * HH];
__device__ __half g_Bh[(size_t)EE * HH * HH];   // [e][n][k], scaled by 4096
__device__ __half g_Bl[(size_t)EE * HH * HH];

// ---------------- helpers ----------------
__device__ __forceinline__ uint32_t smem_u32(const void* p) {
    uint32_t a;
    asm("{ .reg .u64 t; cvta.to.shared.u64 t, %1; cvt.u32.u64 %0, t; }" : "=r"(a) : "l"(p));
    return a;
}
__device__ __forceinline__ uint32_t h2u(__half2 h) { return *(uint32_t*)&h; }

#define CPA(dst, src) \
    asm volatile("cp.async.cg.shared.global [%0], [%1], 16;" :: "r"(dst), "l"(src))
#define CP_COMMIT() asm volatile("cp.async.commit_group;" ::: "memory")
#define CP_WAIT2()  asm volatile("cp.async.wait_group 2;" ::: "memory")

#define LDSM4(r, addr) \
    asm volatile("ldmatrix.sync.aligned.m8n8.x4.shared.b16 {%0,%1,%2,%3}, [%4];" \
                 : "=r"((r)[0]), "=r"((r)[1]), "=r"((r)[2]), "=r"((r)[3]) : "r"(addr))

#define MMA(c, a, b) \
    asm volatile("mma.sync.aligned.m16n8k16.row.col.f32.f16.f16.f32 " \
                 "{%0,%1,%2,%3},{%4,%5,%6,%7},{%8,%9},{%0,%1,%2,%3};" \
                 : "+f"((c)[0]), "+f"((c)[1]), "+f"((c)[2]), "+f"((c)[3]) \
                 : "r"((a)[0]), "r"((a)[1]), "r"((a)[2]), "r"((a)[3]), \
                   "r"((b)[0]), "r"((b)[1]))

// ---------------- kernel 0: reset counters ----------------
__global__ void k_init() {
    if (threadIdx.x < EE) g_counts[threadIdx.x] = 0;
}

// ---------------- kernel 1: x -> fp16 (rn) ----------------
__global__ void k_prep_x(const float* __restrict__ x) {
    size_t idx = (size_t)blockIdx.x * blockDim.x + threadIdx.x;  // float4 index
    float4 v = ((const float4*)x)[idx];
    __half2 h0 = __floats2half2_rn(v.x, v.y);
    __half2 h1 = __floats2half2_rn(v.z, v.w);
    ((uint2*)g_Ah)[idx] = make_uint2(h2u(h0), h2u(h1));
}

// ---------------- kernel 2: We [e][k][n] -> Bh/Bl fp16 [e][n][k], scaled ----------------
__global__ void k_prep_B(const float* __restrict__ We) {
    const int e = blockIdx.z;
    const int k0 = blockIdx.y * 64;
    const int n0 = blockIdx.x * 64;
    __shared__ float t[64][65];
    const int tid = threadIdx.x;
#pragma unroll
    for (int q = 0; q < 16; ++q) {
        int lin = q * 256 + tid;
        int kr = lin >> 6, nc = lin & 63;
        t[kr][nc] = We[((size_t)e * HH + (k0 + kr)) * HH + n0 + nc];
    }
    __syncthreads();
#pragma unroll
    for (int q = 0; q < 8; ++q) {
        int lin = q * 256 + tid;
        int nr = lin >> 5, kc = (lin & 31) * 2;
        float a = t[kc][nr] * BSCALE;
        float b = t[kc + 1][nr] * BSCALE;
        __half2 h = __floats2half2_rn(a, b);
        float2 hf = __half22float2(h);
        __half2 l = __floats2half2_rn(a - hf.x, b - hf.y);
        size_t off = ((size_t)e * HH + (n0 + nr)) * HH + k0 + kc;
        *(uint32_t*)(g_Bh + off) = h2u(h);
        *(uint32_t*)(g_Bl + off) = h2u(l);
    }
}

// ---------------- kernel 3: gating (one warp per token, float4 loads) ----------------
__global__ void k_gate(const float* __restrict__ x,
                       const float* __restrict__ Wg,
                       const float* __restrict__ bg) {
    int gw = (blockIdx.x * blockDim.x + threadIdx.x) >> 5;
    int lane = threadIdx.x & 31;
    if (gw >= TT) return;
    const float4* xr = (const float4*)(x + (size_t)gw * HH);

    float acc[EE];
#pragma unroll
    for (int e = 0; e < EE; ++e) acc[e] = 0.0f;

    for (int h4 = lane; h4 < HH / 4; h4 += 32) {
        float4 xv = xr[h4];
        const float4* w = (const float4*)(Wg + (size_t)h4 * 4 * EE);
        float xs[4] = {xv.x, xv.y, xv.z, xv.w};
#pragma unroll
        for (int r = 0; r < 4; ++r) {
            float4 w0 = w[2 * r], w1 = w[2 * r + 1];
            acc[0] += xs[r] * w0.x; acc[1] += xs[r] * w0.y;
            acc[2] += xs[r] * w0.z; acc[3] += xs[r] * w0.w;
            acc[4] += xs[r] * w1.x; acc[5] += xs[r] * w1.y;
            acc[6] += xs[r] * w1.z; acc[7] += xs[r] * w1.w;
        }
    }
#pragma unroll
    for (int o = 16; o; o >>= 1)
#pragma unroll
        for (int e = 0; e < EE; ++e)
            acc[e] += __shfl_xor_sync(0xffffffffu, acc[e], o);

    if (lane == 0) {
        float m = -1e30f;
#pragma unroll
        for (int e = 0; e < EE; ++e) { acc[e] += bg[e]; m = fmaxf(m, acc[e]); }
        float sc[EE], s = 0.0f;
#pragma unroll
        for (int e = 0; e < EE; ++e) { sc[e] = expf(acc[e] - m); s += sc[e]; }
        float inv = 1.0f / s;
#pragma unroll
        for (int e = 0; e < EE; ++e) sc[e] *= inv;
        int e0 = 0;
#pragma unroll
        for (int e = 1; e < EE; ++e) if (sc[e] > sc[e0]) e0 = e;
        int e1 = (e0 == 0) ? 1 : 0;
#pragma unroll
        for (int e = 0; e < EE; ++e) if (e != e0 && sc[e] > sc[e1]) e1 = e;
        int t = gw;
        g_gate[2 * t + 0] = sc[e0];
        g_gate[2 * t + 1] = sc[e1];
        int p0 = atomicAdd(&g_counts[e0], 1);
        g_list[e0][p0] = 2 * t + 0;
        int p1 = atomicAdd(&g_counts[e1], 1);
        g_list[e1][p1] = 2 * t + 1;
    }
}

// ---------------- kernel 4: fp16 2-term grouped GEMM on HMMA ----------------
__global__ __launch_bounds__(256, 1)
void k_gemm_mma(const float* __restrict__ be) {
    const int e = blockIdx.z;
    const int count = g_counts[e];
    const int row0 = blockIdx.y * BM;
    if (row0 >= count) return;
    const int n0 = blockIdx.x * BN;

    extern __shared__ char smem_raw[];
    const uint32_t sb = smem_u32(smem_raw);
    const int tid = threadIdx.x;
    const int w = tid >> 5, l = tid & 31;

    // cp.async assignments: rows rA+32q, 16B chunk ch; 4 granules per matrix
    const int rA = tid >> 3;
    const int ch = tid & 7;
    const __half* srcA[4];
    const __half* srcBh[4];
    const __half* srcBl[4];
    uint32_t dstoff[4];
#pragma unroll
    for (int q = 0; q < 4; ++q) {
        int r = rA + 32 * q;
        int gr = row0 + r;
        int cl = (gr < count) ? gr : (count - 1);
        int slot = g_list[e][cl];
        srcA[q] = g_Ah + (size_t)(slot >> 1) * HH + ch * 8;
        size_t bbase = ((size_t)e * HH + n0 + r) * HH + ch * 8;
        srcBh[q] = g_Bh + bbase;
        srcBl[q] = g_Bl + bbase;
        dstoff[q] = (uint32_t)r * 128u + (uint32_t)((ch ^ (rA & 7)) << 4);
    }

    auto issue = [&](int s, int c) {
        const uint32_t base = sb + s * STAGE_BYTES;
        const int ke = c * BK;
#pragma unroll
        for (int q = 0; q < 4; ++q) CPA(base + dstoff[q], srcA[q] + ke);
#pragma unroll
        for (int q = 0; q < 4; ++q) CPA(base + MAT_BYTES + dstoff[q], srcBh[q] + ke);
#pragma unroll
        for (int q = 0; q < 4; ++q) CPA(base + 2 * MAT_BYTES + dstoff[q], srcBl[q] + ke);
    };

    // prologue: 3 stages in flight
    issue(0, 0); CP_COMMIT();
    issue(1, 1); CP_COMMIT();
    issue(2, 2); CP_COMMIT();

    // per-warp tile: 64 rows x 32 cols
    const int m_base = (w & 1) * 64;
    const int n_base = (w >> 1) * 32;

    uint32_t rowA[4], rowB[2], xoA[4], xoB[4];
#pragma unroll
    for (int i = 0; i < 4; ++i) rowA[i] = (uint32_t)(m_base + 16 * i + (l & 15)) * 128u;
#pragma unroll
    for (int j2 = 0; j2 < 2; ++j2)
        rowB[j2] = (uint32_t)(n_base + 16 * j2 + (l & 7) + ((l >> 4) << 3)) * 128u;
#pragma unroll
    for (int ks = 0; ks < 4; ++ks) {
        xoA[ks] = (uint32_t)(((ks * 2 + (l >> 4)) ^ (l & 7)) << 4);
        xoB[ks] = (uint32_t)(((ks * 2 + ((l >> 3) & 1)) ^ (l & 7)) << 4);
    }

    float acc[4][4][4];
#pragma unroll
    for (int i = 0; i < 4; ++i)
#pragma unroll
        for (int j = 0; j < 4; ++j)
#pragma unroll
            for (int q = 0; q < 4; ++q) acc[i][j][q] = 0.0f;

    // double-buffered fragments
    uint32_t fa[2][4][4], fb[2][2][4], fl[2][2][4];

    for (int c = 0; c < NCH; ++c) {
        CP_WAIT2();
        __syncthreads();
        if (c + 3 < NCH) issue((c + 3) % STG, c + 3);
        CP_COMMIT();

        const uint32_t Ah = sb + (c % STG) * STAGE_BYTES;
        const uint32_t Bh = Ah + MAT_BYTES;
        const uint32_t Bl = Ah + 2 * MAT_BYTES;

        // load k-step 0 fragments
#pragma unroll
        for (int i = 0; i < 4; ++i) LDSM4(fa[0][i], Ah + rowA[i] + xoA[0]);
#pragma unroll
        for (int j2 = 0; j2 < 2; ++j2) {
            LDSM4(fb[0][j2], Bh + rowB[j2] + xoB[0]);
            LDSM4(fl[0][j2], Bl + rowB[j2] + xoB[0]);
        }

#pragma unroll
        for (int ks = 0; ks < 4; ++ks) {
            const int cur = ks & 1, nxt = cur ^ 1;
            if (ks < 3) {
#pragma unroll
                for (int i = 0; i < 4; ++i) LDSM4(fa[nxt][i], Ah + rowA[i] + xoA[ks + 1]);
#pragma unroll
                for (int j2 = 0; j2 < 2; ++j2) {
                    LDSM4(fb[nxt][j2], Bh + rowB[j2] + xoB[ks + 1]);
                    LDSM4(fl[nxt][j2], Bl + rowB[j2] + xoB[ks + 1]);
                }
            }
#pragma unroll
            for (int i = 0; i < 4; ++i) {
#pragma unroll
                for (int j = 0; j < 4; ++j) {
                    uint32_t* bh = &fb[cur][j >> 1][(j & 1) * 2];
                    uint32_t* bl = &fl[cur][j >> 1][(j & 1) * 2];
                    MMA(acc[i][j], fa[cur][i], bh);
                    MMA(acc[i][j], fa[cur][i], bl);
                }
            }
        }
    }

    // epilogue: Y[slot] = gate * (acc/BSCALE + be)
    float2 bias[4];
#pragma unroll
    for (int j = 0; j < 4; ++j) {
        int col = n_base + 8 * j + 2 * (l & 3);
        bias[j] = *(const float2*)(be + (size_t)e * HH + n0 + col);
    }
#pragma unroll
    for (int i = 0; i < 4; ++i) {
#pragma unroll
        for (int half = 0; half < 2; ++half) {
            int r = m_base + 16 * i + (l >> 2) + 8 * half;
            int gr = row0 + r;
            if (gr < count) {
                int slot = g_list[e][gr];
                float gate = g_gate[slot];
                float gs = gate * INV_BSCALE;
                float* yr = g_Y + (size_t)slot * HH + n0;
#pragma unroll
                for (int j = 0; j < 4; ++j) {
                    int col = n_base + 8 * j + 2 * (l & 3);
                    float2 o;
                    o.x = gs * acc[i][j][half * 2 + 0] + gate * bias[j].x;
                    o.y = gs * acc[i][j][half * 2 + 1] + gate * bias[j].y;
                    *(float2*)(yr + col) = o;
                }
            }
        }
    }
}

// ---------------- kernel 5: combine ----------------
__global__ void k_combine(float* __restrict__ out) {
    size_t i = (size_t)blockIdx.x * blockDim.x + threadIdx.x;
    const size_t H4 = HH / 4;
    size_t t = i / H4;
    size_t h4 = i - t * H4;
    const float4* Y4 = (const float4*)g_Y;
    float4 a = Y4[(2 * t) * H4 + h4];
    float4 b = Y4[(2 * t + 1) * H4 + h4];
    ((float4*)out)[i] = make_float4(a.x + b.x, a.y + b.y, a.z + b.z, a.w + b.w);
}

// ---------------- launch ----------------
extern "C" void kernel_launch(void* const* d_in, const int* in_sizes, int n_in,
                              void* d_out, int out_size) {
    const float* x  = (const float*)d_in[0];
    const float* Wg = (const float*)d_in[1];
    const float* bg = (const float*)d_in[2];
    const float* We = (const float*)d_in[3];
    const float* be = (const float*)d_in[4];
    float* out = (float*)d_out;

    cudaFuncSetAttribute(k_gemm_mma, cudaFuncAttributeMaxDynamicSharedMemorySize, SMEM_NEED);

    k_init<<<1, 32>>>();
    k_prep_x<<<(TT * HH / 4) / 256, 256>>>(x);
    k_prep_B<<<dim3(HH / 64, HH / 64, EE), 256>>>(We);
    k_gate<<<TT / 8, 256>>>(x, Wg, bg);
    k_gemm_mma<<<dim3(HH / BN, TT / BM, EE), 256, SMEM_NEED>>>(be);
    k_combine<<<(TT * (HH / 4)) / 256, 256>>>(out);
}

// round 8
// speedup vs baseline: 3.5198x; 1.0914x over previous
#include <cuda_runtime.h>
#include <cuda_fp16.h>
#include <cstdint>

// Problem constants
#define TT 8192
#define HH 2048
#define EE 8

// GEMM config
#define BM 128
#define BN 128
#define BK 64
#define NCH (HH / BK)          // 32 k-chunks
#define STG 4
#define MAT_BYTES 16384        // 128 rows x 128B (64 fp16)
#define STAGE_BYTES (3 * MAT_BYTES)       // Ah, Bh, Bl
#define SMEM_NEED (STG * STAGE_BYTES)     // 196608
#define BSCALE 4096.0f
#define INV_BSCALE (1.0f / 4096.0f)

// ---------------- static scratch ----------------
__device__ int    g_counts[EE];
__device__ int    g_list[EE][TT];
__device__ float  g_gate[2 * TT];
__device__ float  g_Y[(size_t)2 * TT * HH];
__device__ __half g_Ah[(size_t)TT * HH];
__device__ __half g_Bh[(size_t)EE * HH * HH];   // [e][n][k], scaled by 4096
__device__ __half g_Bl[(size_t)EE * HH * HH];

// ---------------- helpers ----------------
__device__ __forceinline__ uint32_t smem_u32(const void* p) {
    uint32_t a;
    asm("{ .reg .u64 t; cvta.to.shared.u64 t, %1; cvt.u32.u64 %0, t; }" : "=r"(a) : "l"(p));
    return a;
}
__device__ __forceinline__ uint32_t h2u(__half2 h) { return *(uint32_t*)&h; }

#define CPA(dst, src) \
    asm volatile("cp.async.cg.shared.global [%0], [%1], 16;" :: "r"(dst), "l"(src))
#define CP_COMMIT() asm volatile("cp.async.commit_group;" ::: "memory")
#define CP_WAIT2()  asm volatile("cp.async.wait_group 2;" ::: "memory")

#define LDSM4(r, addr) \
    asm volatile("ldmatrix.sync.aligned.m8n8.x4.shared.b16 {%0,%1,%2,%3}, [%4];" \
                 : "=r"((r)[0]), "=r"((r)[1]), "=r"((r)[2]), "=r"((r)[3]) : "r"(addr))

#define MMA(c, a, b) \
    asm volatile("mma.sync.aligned.m16n8k16.row.col.f32.f16.f16.f32 " \
                 "{%0,%1,%2,%3},{%4,%5,%6,%7},{%8,%9},{%0,%1,%2,%3};" \
                 : "+f"((c)[0]), "+f"((c)[1]), "+f"((c)[2]), "+f"((c)[3]) \
                 : "r"((a)[0]), "r"((a)[1]), "r"((a)[2]), "r"((a)[3]), \
                   "r"((b)[0]), "r"((b)[1]))

// ---------------- kernel 0: reset counters ----------------
__global__ void k_init() {
    if (threadIdx.x < EE) g_counts[threadIdx.x] = 0;
}

// ---------------- kernel 1: x -> fp16 (rn) ----------------
__global__ void k_prep_x(const float* __restrict__ x) {
    size_t idx = (size_t)blockIdx.x * blockDim.x + threadIdx.x;  // float4 index
    float4 v = ((const float4*)x)[idx];
    __half2 h0 = __floats2half2_rn(v.x, v.y);
    __half2 h1 = __floats2half2_rn(v.z, v.w);
    ((uint2*)g_Ah)[idx] = make_uint2(h2u(h0), h2u(h1));
}

// ---------------- kernel 2: We [e][k][n] -> Bh/Bl fp16 [e][n][k], scaled ----------------
// 512 threads, two 64x64 tiles per block (stacked along k)
__global__ __launch_bounds__(512, 1)
void k_prep_B(const float* __restrict__ We) {
    const int e = blockIdx.z;
    const int k0 = blockIdx.y * 128 + (threadIdx.x >> 8) * 64;
    const int n0 = blockIdx.x * 64;
    __shared__ float t[2][64][65];
    float (*tt)[65] = t[threadIdx.x >> 8];
    const int tid = threadIdx.x & 255;
#pragma unroll
    for (int q = 0; q < 16; ++q) {
        int lin = q * 256 + tid;
        int kr = lin >> 6, nc = lin & 63;
        tt[kr][nc] = We[((size_t)e * HH + (k0 + kr)) * HH + n0 + nc];
    }
    __syncthreads();
#pragma unroll
    for (int q = 0; q < 8; ++q) {
        int lin = q * 256 + tid;
        int nr = lin >> 5, kc = (lin & 31) * 2;
        float a = tt[kc][nr] * BSCALE;
        float b = tt[kc + 1][nr] * BSCALE;
        __half2 h = __floats2half2_rn(a, b);
        float2 hf = __half22float2(h);
        __half2 l = __floats2half2_rn(a - hf.x, b - hf.y);
        size_t off = ((size_t)e * HH + (n0 + nr)) * HH + k0 + kc;
        *(uint32_t*)(g_Bh + off) = h2u(h);
        *(uint32_t*)(g_Bl + off) = h2u(l);
    }
}

// ---------------- kernel 3: gating (one warp per token; R4 form, 54us measured) ------
__global__ void k_gate(const float* __restrict__ x,
                       const float* __restrict__ Wg,
                       const float* __restrict__ bg) {
    int gw = (blockIdx.x * blockDim.x + threadIdx.x) >> 5;
    int lane = threadIdx.x & 31;
    if (gw >= TT) return;
    const float* xr = x + (size_t)gw * HH;

    float acc[EE];
#pragma unroll
    for (int e = 0; e < EE; ++e) acc[e] = 0.0f;
    for (int h = lane; h < HH; h += 32) {
        float xv = xr[h];
        const float4* w4 = (const float4*)(Wg + (size_t)h * EE);
        float4 w0 = w4[0], w1 = w4[1];
        acc[0] += xv * w0.x; acc[1] += xv * w0.y;
        acc[2] += xv * w0.z; acc[3] += xv * w0.w;
        acc[4] += xv * w1.x; acc[5] += xv * w1.y;
        acc[6] += xv * w1.z; acc[7] += xv * w1.w;
    }
#pragma unroll
    for (int o = 16; o; o >>= 1)
#pragma unroll
        for (int e = 0; e < EE; ++e)
            acc[e] += __shfl_xor_sync(0xffffffffu, acc[e], o);

    if (lane == 0) {
        float m = -1e30f;
#pragma unroll
        for (int e = 0; e < EE; ++e) { acc[e] += bg[e]; m = fmaxf(m, acc[e]); }
        float sc[EE], s = 0.0f;
#pragma unroll
        for (int e = 0; e < EE; ++e) { sc[e] = expf(acc[e] - m); s += sc[e]; }
        float inv = 1.0f / s;
#pragma unroll
        for (int e = 0; e < EE; ++e) sc[e] *= inv;
        int e0 = 0;
#pragma unroll
        for (int e = 1; e < EE; ++e) if (sc[e] > sc[e0]) e0 = e;
        int e1 = (e0 == 0) ? 1 : 0;
#pragma unroll
        for (int e = 0; e < EE; ++e) if (e != e0 && sc[e] > sc[e1]) e1 = e;
        int t = gw;
        g_gate[2 * t + 0] = sc[e0];
        g_gate[2 * t + 1] = sc[e1];
        int p0 = atomicAdd(&g_counts[e0], 1);
        g_list[e0][p0] = 2 * t + 0;
        int p1 = atomicAdd(&g_counts[e1], 1);
        g_list[e1][p1] = 2 * t + 1;
    }
}

// ---------------- kernel 4: fp16 2-term grouped GEMM on HMMA ----------------
__global__ __launch_bounds__(256, 1)
void k_gemm_mma(const float* __restrict__ be) {
    const int e = blockIdx.z;
    const int count = g_counts[e];
    const int row0 = blockIdx.y * BM;
    if (row0 >= count) return;
    const int n0 = blockIdx.x * BN;

    extern __shared__ char smem_raw[];
    const uint32_t sb = smem_u32(smem_raw);
    const int tid = threadIdx.x;
    const int w = tid >> 5, l = tid & 31;

    // cp.async assignments: rows rA+32q, 16B chunk ch; 4 granules per matrix
    const int rA = tid >> 3;
    const int ch = tid & 7;
    const __half* srcA[4];
    const __half* srcBh[4];
    const __half* srcBl[4];
    uint32_t dstoff[4];
#pragma unroll
    for (int q = 0; q < 4; ++q) {
        int r = rA + 32 * q;
        int gr = row0 + r;
        int cl = (gr < count) ? gr : (count - 1);
        int slot = g_list[e][cl];
        srcA[q] = g_Ah + (size_t)(slot >> 1) * HH + ch * 8;
        size_t bbase = ((size_t)e * HH + n0 + r) * HH + ch * 8;
        srcBh[q] = g_Bh + bbase;
        srcBl[q] = g_Bl + bbase;
        dstoff[q] = (uint32_t)r * 128u + (uint32_t)((ch ^ (rA & 7)) << 4);
    }

    auto issue = [&](int s, int c) {
        const uint32_t base = sb + s * STAGE_BYTES;
        const int ke = c * BK;
#pragma unroll
        for (int q = 0; q < 4; ++q) CPA(base + dstoff[q], srcA[q] + ke);
#pragma unroll
        for (int q = 0; q < 4; ++q) CPA(base + MAT_BYTES + dstoff[q], srcBh[q] + ke);
#pragma unroll
        for (int q = 0; q < 4; ++q) CPA(base + 2 * MAT_BYTES + dstoff[q], srcBl[q] + ke);
    };

    // prologue: 3 stages in flight
    issue(0, 0); CP_COMMIT();
    issue(1, 1); CP_COMMIT();
    issue(2, 2); CP_COMMIT();

    // per-warp tile: 64 rows x 32 cols
    const int m_base = (w & 1) * 64;
    const int n_base = (w >> 1) * 32;

    uint32_t rowA[4], rowB[2], xoA[4], xoB[4];
#pragma unroll
    for (int i = 0; i < 4; ++i) rowA[i] = (uint32_t)(m_base + 16 * i + (l & 15)) * 128u;
#pragma unroll
    for (int j2 = 0; j2 < 2; ++j2)
        rowB[j2] = (uint32_t)(n_base + 16 * j2 + (l & 7) + ((l >> 4) << 3)) * 128u;
#pragma unroll
    for (int ks = 0; ks < 4; ++ks) {
        xoA[ks] = (uint32_t)(((ks * 2 + (l >> 4)) ^ (l & 7)) << 4);
        xoB[ks] = (uint32_t)(((ks * 2 + ((l >> 3) & 1)) ^ (l & 7)) << 4);
    }

    float acc[4][4][4];
#pragma unroll
    for (int i = 0; i < 4; ++i)
#pragma unroll
        for (int j = 0; j < 4; ++j)
#pragma unroll
            for (int q = 0; q < 4; ++q) acc[i][j][q] = 0.0f;

    // double-buffered fragments
    uint32_t fa[2][4][4], fb[2][2][4], fl[2][2][4];

    for (int c = 0; c < NCH; ++c) {
        CP_WAIT2();
        __syncthreads();
        if (c + 3 < NCH) issue((c + 3) % STG, c + 3);
        CP_COMMIT();

        const uint32_t Ah = sb + (c % STG) * STAGE_BYTES;
        const uint32_t Bh = Ah + MAT_BYTES;
        const uint32_t Bl = Ah + 2 * MAT_BYTES;

        // load k-step 0 fragments
#pragma unroll
        for (int i = 0; i < 4; ++i) LDSM4(fa[0][i], Ah + rowA[i] + xoA[0]);
#pragma unroll
        for (int j2 = 0; j2 < 2; ++j2) {
            LDSM4(fb[0][j2], Bh + rowB[j2] + xoB[0]);
            LDSM4(fl[0][j2], Bl + rowB[j2] + xoB[0]);
        }

#pragma unroll
        for (int ks = 0; ks < 4; ++ks) {
            const int cur = ks & 1, nxt = cur ^ 1;
            if (ks < 3) {
#pragma unroll
                for (int i = 0; i < 4; ++i) LDSM4(fa[nxt][i], Ah + rowA[i] + xoA[ks + 1]);
#pragma unroll
                for (int j2 = 0; j2 < 2; ++j2) {
                    LDSM4(fb[nxt][j2], Bh + rowB[j2] + xoB[ks + 1]);
                    LDSM4(fl[nxt][j2], Bl + rowB[j2] + xoB[ks + 1]);
                }
            }
#pragma unroll
            for (int i = 0; i < 4; ++i) {
#pragma unroll
                for (int j = 0; j < 4; ++j) {
                    uint32_t* bh = &fb[cur][j >> 1][(j & 1) * 2];
                    uint32_t* bl = &fl[cur][j >> 1][(j & 1) * 2];
                    MMA(acc[i][j], fa[cur][i], bh);
                    MMA(acc[i][j], fa[cur][i], bl);
                }
            }
        }
    }

    // epilogue: Y[slot] = gate * (acc/BSCALE + be)
    float2 bias[4];
#pragma unroll
    for (int j = 0; j < 4; ++j) {
        int col = n_base + 8 * j + 2 * (l & 3);
        bias[j] = *(const float2*)(be + (size_t)e * HH + n0 + col);
    }
#pragma unroll
    for (int i = 0; i < 4; ++i) {
#pragma unroll
        for (int half = 0; half < 2; ++half) {
            int r = m_base + 16 * i + (l >> 2) + 8 * half;
            int gr = row0 + r;
            if (gr < count) {
                int slot = g_list[e][gr];
                float gate = g_gate[slot];
                float gs = gate * INV_BSCALE;
                float* yr = g_Y + (size_t)slot * HH + n0;
#pragma unroll
                for (int j = 0; j < 4; ++j) {
                    int col = n_base + 8 * j + 2 * (l & 3);
                    float2 o;
                    o.x = gs * acc[i][j][half * 2 + 0] + gate * bias[j].x;
                    o.y = gs * acc[i][j][half * 2 + 1] + gate * bias[j].y;
                    *(float2*)(yr + col) = o;
                }
            }
        }
    }
}

// ---------------- kernel 5: combine ----------------
__global__ void k_combine(float* __restrict__ out) {
    size_t i = (size_t)blockIdx.x * blockDim.x + threadIdx.x;
    const size_t H4 = HH / 4;
    size_t t = i / H4;
    size_t h4 = i - t * H4;
    const float4* Y4 = (const float4*)g_Y;
    float4 a = Y4[(2 * t) * H4 + h4];
    float4 b = Y4[(2 * t + 1) * H4 + h4];
    ((float4*)out)[i] = make_float4(a.x + b.x, a.y + b.y, a.z + b.z, a.w + b.w);
}

// ---------------- launch ----------------
extern "C" void kernel_launch(void* const* d_in, const int* in_sizes, int n_in,
                              void* d_out, int out_size) {
    const float* x  = (const float*)d_in[0];
    const float* Wg = (const float*)d_in[1];
    const float* bg = (const float*)d_in[2];
    const float* We = (const float*)d_in[3];
    const float* be = (const float*)d_in[4];
    float* out = (float*)d_out;

    cudaFuncSetAttribute(k_gemm_mma, cudaFuncAttributeMaxDynamicSharedMemorySize, SMEM_NEED);

    k_init<<<1, 32>>>();
    k_prep_x<<<(TT * HH / 4) / 256, 256>>>(x);
    k_prep_B<<<dim3(HH / 64, HH / 128, EE), 512>>>(We);
    k_gate<<<TT / 8, 256>>>(x, Wg, bg);
    k_gemm_mma<<<dim3(HH / BN, TT / BM, EE), 256, SMEM_NEED>>>(be);
    k_combine<<<(TT * (HH / 4)) / 256, 256>>>(out);
}

// round 12
// speedup vs baseline: 3.5467x; 1.0076x over previous
#include <cuda_runtime.h>
#include <cuda_fp16.h>
#include <cstdint>

// Problem constants
#define TT 8192
#define HH 2048
#define EE 8

// GEMM config
#define BM 128
#define BN 128
#define BK 64
#define NCH (HH / BK)          // 32 k-chunks
#define STG 4
#define MAT_BYTES 16384        // 128 rows x 128B (64 fp16)
#define STAGE_BYTES (3 * MAT_BYTES)       // Ah, Bh, Bl
#define SMEM_NEED (STG * STAGE_BYTES)     // 196608
#define BSCALE 4096.0f
#define INV_BSCALE (1.0f / 4096.0f)

// ---------------- static scratch ----------------
__device__ int    g_counts[EE];
__device__ int    g_list[EE][TT];
__device__ float  g_gate[2 * TT];
__device__ __half g_Ah[(size_t)TT * HH];
__device__ __half g_Bh[(size_t)EE * HH * HH];   // [e][n][k], scaled by 4096
__device__ __half g_Bl[(size_t)EE * HH * HH];

// ---------------- helpers ----------------
__device__ __forceinline__ uint32_t smem_u32(const void* p) {
    uint32_t a;
    asm("{ .reg .u64 t; cvta.to.shared.u64 t, %1; cvt.u32.u64 %0, t; }" : "=r"(a) : "l"(p));
    return a;
}
__device__ __forceinline__ uint32_t h2u(__half2 h) { return *(uint32_t*)&h; }

#define CPA(dst, src) \
    asm volatile("cp.async.cg.shared.global [%0], [%1], 16;" :: "r"(dst), "l"(src))
#define CP_COMMIT() asm volatile("cp.async.commit_group;" ::: "memory")
#define CP_WAIT2()  asm volatile("cp.async.wait_group 2;" ::: "memory")

#define LDSM4(r, addr) \
    asm volatile("ldmatrix.sync.aligned.m8n8.x4.shared.b16 {%0,%1,%2,%3}, [%4];" \
                 : "=r"((r)[0]), "=r"((r)[1]), "=r"((r)[2]), "=r"((r)[3]) : "r"(addr))

#define MMA(c, a, b) \
    asm volatile("mma.sync.aligned.m16n8k16.row.col.f32.f16.f16.f32 " \
                 "{%0,%1,%2,%3},{%4,%5,%6,%7},{%8,%9},{%0,%1,%2,%3};" \
                 : "+f"((c)[0]), "+f"((c)[1]), "+f"((c)[2]), "+f"((c)[3]) \
                 : "r"((a)[0]), "r"((a)[1]), "r"((a)[2]), "r"((a)[3]), \
                   "r"((b)[0]), "r"((b)[1]))

#define REDADD(ptr, val) \
    asm volatile("red.global.add.f32 [%0], %1;" :: "l"(ptr), "f"(val) : "memory")

// ---------------- kernel 0: zero output + reset counters ----------------
__global__ void k_zero(float* __restrict__ out) {
    if (blockIdx.x == 0 && threadIdx.x < EE) g_counts[threadIdx.x] = 0;
    size_t i = (size_t)blockIdx.x * blockDim.x + threadIdx.x;   // float4 index
    ((float4*)out)[i] = make_float4(0.f, 0.f, 0.f, 0.f);
}

// ---------------- kernel 1: x -> fp16 (rn) ----------------
__global__ void k_prep_x(const float* __restrict__ x) {
    size_t idx = (size_t)blockIdx.x * blockDim.x + threadIdx.x;  // float4 index
    float4 v = ((const float4*)x)[idx];
    __half2 h0 = __floats2half2_rn(v.x, v.y);
    __half2 h1 = __floats2half2_rn(v.z, v.w);
    ((uint2*)g_Ah)[idx] = make_uint2(h2u(h0), h2u(h1));
}

// ---------------- kernel 2: We [e][k][n] -> Bh/Bl fp16 [e][n][k], scaled ----------------
__global__ __launch_bounds__(512, 1)
void k_prep_B(const float* __restrict__ We) {
    const int e = blockIdx.z;
    const int k0 = blockIdx.y * 128 + (threadIdx.x >> 8) * 64;
    const int n0 = blockIdx.x * 64;
    __shared__ float t[2][64][65];
    float (*tt)[65] = t[threadIdx.x >> 8];
    const int tid = threadIdx.x & 255;
#pragma unroll
    for (int q = 0; q < 16; ++q) {
        int lin = q * 256 + tid;
        int kr = lin >> 6, nc = lin & 63;
        tt[kr][nc] = We[((size_t)e * HH + (k0 + kr)) * HH + n0 + nc];
    }
    __syncthreads();
#pragma unroll
    for (int q = 0; q < 8; ++q) {
        int lin = q * 256 + tid;
        int nr = lin >> 5, kc = (lin & 31) * 2;
        float a = tt[kc][nr] * BSCALE;
        float b = tt[kc + 1][nr] * BSCALE;
        __half2 h = __floats2half2_rn(a, b);
        float2 hf = __half22float2(h);
        __half2 l = __floats2half2_rn(a - hf.x, b - hf.y);
        size_t off = ((size_t)e * HH + (n0 + nr)) * HH + k0 + kc;
        *(uint32_t*)(g_Bh + off) = h2u(h);
        *(uint32_t*)(g_Bl + off) = h2u(l);
    }
}

// ---------------- kernel 3: gating (one warp per token; measured-good R4 form) ------
__global__ void k_gate(const float* __restrict__ x,
                       const float* __restrict__ Wg,
                       const float* __restrict__ bg) {
    int gw = (blockIdx.x * blockDim.x + threadIdx.x) >> 5;
    int lane = threadIdx.x & 31;
    if (gw >= TT) return;
    const float* xr = x + (size_t)gw * HH;

    float acc[EE];
#pragma unroll
    for (int e = 0; e < EE; ++e) acc[e] = 0.0f;
    for (int h = lane; h < HH; h += 32) {
        float xv = xr[h];
        const float4* w4 = (const float4*)(Wg + (size_t)h * EE);
        float4 w0 = w4[0], w1 = w4[1];
        acc[0] += xv * w0.x; acc[1] += xv * w0.y;
        acc[2] += xv * w0.z; acc[3] += xv * w0.w;
        acc[4] += xv * w1.x; acc[5] += xv * w1.y;
        acc[6] += xv * w1.z; acc[7] += xv * w1.w;
    }
#pragma unroll
    for (int o = 16; o; o >>= 1)
#pragma unroll
        for (int e = 0; e < EE; ++e)
            acc[e] += __shfl_xor_sync(0xffffffffu, acc[e], o);

    if (lane == 0) {
        float m = -1e30f;
#pragma unroll
        for (int e = 0; e < EE; ++e) { acc[e] += bg[e]; m = fmaxf(m, acc[e]); }
        float sc[EE], s = 0.0f;
#pragma unroll
        for (int e = 0; e < EE; ++e) { sc[e] = expf(acc[e] - m); s += sc[e]; }
        float inv = 1.0f / s;
#pragma unroll
        for (int e = 0; e < EE; ++e) sc[e] *= inv;
        int e0 = 0;
#pragma unroll
        for (int e = 1; e < EE; ++e) if (sc[e] > sc[e0]) e0 = e;
        int e1 = (e0 == 0) ? 1 : 0;
#pragma unroll
        for (int e = 0; e < EE; ++e) if (e != e0 && sc[e] > sc[e1]) e1 = e;
        int t = gw;
        g_gate[2 * t + 0] = sc[e0];
        g_gate[2 * t + 1] = sc[e1];
        int p0 = atomicAdd(&g_counts[e0], 1);
        g_list[e0][p0] = 2 * t + 0;
        int p1 = atomicAdd(&g_counts[e1], 1);
        g_list[e1][p1] = 2 * t + 1;
    }
}

// ---------------- kernel 4: fp16 2-term grouped GEMM, atomic-add epilogue ----------------
__global__ __launch_bounds__(256, 1)
void k_gemm_mma(const float* __restrict__ be, float* __restrict__ out) {
    const int e = blockIdx.z;
    const int count = g_counts[e];
    const int row0 = blockIdx.y * BM;
    if (row0 >= count) return;
    const int n0 = blockIdx.x * BN;

    extern __shared__ char smem_raw[];
    const uint32_t sb = smem_u32(smem_raw);
    const int tid = threadIdx.x;
    const int w = tid >> 5, l = tid & 31;

    // cp.async assignments: rows rA+32q, 16B chunk ch; 4 granules per matrix
    const int rA = tid >> 3;
    const int ch = tid & 7;
    const __half* srcA[4];
    const __half* srcBh[4];
    const __half* srcBl[4];
    uint32_t dstoff[4];
#pragma unroll
    for (int q = 0; q < 4; ++q) {
        int r = rA + 32 * q;
        int gr = row0 + r;
        int cl = (gr < count) ? gr : (count - 1);
        int slot = g_list[e][cl];
        srcA[q] = g_Ah + (size_t)(slot >> 1) * HH + ch * 8;
        size_t bbase = ((size_t)e * HH + n0 + r) * HH + ch * 8;
        srcBh[q] = g_Bh + bbase;
        srcBl[q] = g_Bl + bbase;
        dstoff[q] = (uint32_t)r * 128u + (uint32_t)((ch ^ (rA & 7)) << 4);
    }

    auto issue = [&](int s, int c) {
        const uint32_t base = sb + s * STAGE_BYTES;
        const int ke = c * BK;
#pragma unroll
        for (int q = 0; q < 4; ++q) CPA(base + dstoff[q], srcA[q] + ke);
#pragma unroll
        for (int q = 0; q < 4; ++q) CPA(base + MAT_BYTES + dstoff[q], srcBh[q] + ke);
#pragma unroll
        for (int q = 0; q < 4; ++q) CPA(base + 2 * MAT_BYTES + dstoff[q], srcBl[q] + ke);
    };

    issue(0, 0); CP_COMMIT();
    issue(1, 1); CP_COMMIT();
    issue(2, 2); CP_COMMIT();

    // per-warp tile: 64 rows x 32 cols
    const int m_base = (w & 1) * 64;
    const int n_base = (w >> 1) * 32;

    uint32_t rowA[4], rowB[2], xoA[4], xoB[4];
#pragma unroll
    for (int i = 0; i < 4; ++i) rowA[i] = (uint32_t)(m_base + 16 * i + (l & 15)) * 128u;
#pragma unroll
    for (int j2 = 0; j2 < 2; ++j2)
        rowB[j2] = (uint32_t)(n_base + 16 * j2 + (l & 7) + ((l >> 4) << 3)) * 128u;
#pragma unroll
    for (int ks = 0; ks < 4; ++ks) {
        xoA[ks] = (uint32_t)(((ks * 2 + (l >> 4)) ^ (l & 7)) << 4);
        xoB[ks] = (uint32_t)(((ks * 2 + ((l >> 3) & 1)) ^ (l & 7)) << 4);
    }

    float acc[4][4][4];
#pragma unroll
    for (int i = 0; i < 4; ++i)
#pragma unroll
        for (int j = 0; j < 4; ++j)
#pragma unroll
            for (int q = 0; q < 4; ++q) acc[i][j][q] = 0.0f;

    uint32_t fa[2][4][4], fb[2][2][4], fl[2][2][4];

    for (int c = 0; c < NCH; ++c) {
        CP_WAIT2();
        __syncthreads();
        if (c + 3 < NCH) issue((c + 3) % STG, c + 3);
        CP_COMMIT();

        const uint32_t Ah = sb + (c % STG) * STAGE_BYTES;
        const uint32_t Bh = Ah + MAT_BYTES;
        const uint32_t Bl = Ah + 2 * MAT_BYTES;

#pragma unroll
        for (int i = 0; i < 4; ++i) LDSM4(fa[0][i], Ah + rowA[i] + xoA[0]);
#pragma unroll
        for (int j2 = 0; j2 < 2; ++j2) {
            LDSM4(fb[0][j2], Bh + rowB[j2] + xoB[0]);
            LDSM4(fl[0][j2], Bl + rowB[j2] + xoB[0]);
        }

#pragma unroll
        for (int ks = 0; ks < 4; ++ks) {
            const int cur = ks & 1, nxt = cur ^ 1;
            if (ks < 3) {
#pragma unroll
                for (int i = 0; i < 4; ++i) LDSM4(fa[nxt][i], Ah + rowA[i] + xoA[ks + 1]);
#pragma unroll
                for (int j2 = 0; j2 < 2; ++j2) {
                    LDSM4(fb[nxt][j2], Bh + rowB[j2] + xoB[ks + 1]);
                    LDSM4(fl[nxt][j2], Bl + rowB[j2] + xoB[ks + 1]);
                }
            }
#pragma unroll
            for (int i = 0; i < 4; ++i) {
#pragma unroll
                for (int j = 0; j < 4; ++j) {
                    uint32_t* bh = &fb[cur][j >> 1][(j & 1) * 2];
                    uint32_t* bl = &fl[cur][j >> 1][(j & 1) * 2];
                    MMA(acc[i][j], fa[cur][i], bh);
                    MMA(acc[i][j], fa[cur][i], bl);
                }
            }
        }
    }

    // epilogue: out[token] += gate * (acc/BSCALE + be)   (exactly 2 adds/elem -> deterministic)
    float2 bias[4];
#pragma unroll
    for (int j = 0; j < 4; ++j) {
        int col = n_base + 8 * j + 2 * (l & 3);
        bias[j] = *(const float2*)(be + (size_t)e * HH + n0 + col);
    }
#pragma unroll
    for (int i = 0; i < 4; ++i) {
#pragma unroll
        for (int half = 0; half < 2; ++half) {
            int r = m_base + 16 * i + (l >> 2) + 8 * half;
            int gr = row0 + r;
            if (gr < count) {
                int slot = g_list[e][gr];
                float gate = g_gate[slot];
                float gs = gate * INV_BSCALE;
                float* yr = out + (size_t)(slot >> 1) * HH + n0;
#pragma unroll
                for (int j = 0; j < 4; ++j) {
                    int col = n_base + 8 * j + 2 * (l & 3);
                    float vx = gs * acc[i][j][half * 2 + 0] + gate * bias[j].x;
                    float vy = gs * acc[i][j][half * 2 + 1] + gate * bias[j].y;
                    REDADD(yr + col, vx);
                    REDADD(yr + col + 1, vy);
                }
            }
        }
    }
}

// ---------------- launch ----------------
extern "C" void kernel_launch(void* const* d_in, const int* in_sizes, int n_in,
                              void* d_out, int out_size) {
    const float* x  = (const float*)d_in[0];
    const float* Wg = (const float*)d_in[1];
    const float* bg = (const float*)d_in[2];
    const float* We = (const float*)d_in[3];
    const float* be = (const float*)d_in[4];
    float* out = (float*)d_out;

    cudaFuncSetAttribute(k_gemm_mma, cudaFuncAttributeMaxDynamicSharedMemorySize, SMEM_NEED);

    k_zero<<<(TT * (HH / 4)) / 256, 256>>>(out);
    k_prep_x<<<(TT * HH / 4) / 256, 256>>>(x);
    k_prep_B<<<dim3(HH / 64, HH / 128, EE), 512>>>(We);
    k_gate<<<TT / 8, 256>>>(x, Wg, bg);
    k_gemm_mma<<<dim3(HH / BN, TT / BM, EE), 256, SMEM_NEED>>>(be, out);
}

// round 13
// speedup vs baseline: 4.1071x; 1.1580x over previous
#include <cuda_runtime.h>
#include <cuda_fp16.h>
#include <cstdint>

// Problem constants
#define TT 8192
#define HH 2048
#define EE 8

// GEMM config
#define BM 128
#define BN 128
#define BK 64
#define NCH (HH / BK)          // 32 k-chunks
#define STG 2
#define MAT_BYTES 16384        // 128 rows x 128B (64 fp16)
#define STAGE_BYTES (3 * MAT_BYTES)       // Ah, Bh, Bl  (48KB)
#define SMEM_NEED (STG * STAGE_BYTES)     // 98304 -> 2 CTAs/SM
#define BSCALE 4096.0f
#define INV_BSCALE (1.0f / 4096.0f)

// ---------------- static scratch ----------------
__device__ int    g_counts[EE];
__device__ int    g_list[EE][TT];
__device__ float  g_gate[2 * TT];
__device__ __half g_Ah[(size_t)TT * HH];
__device__ __half g_Bh[(size_t)EE * HH * HH];   // [e][n][k], scaled by 4096
__device__ __half g_Bl[(size_t)EE * HH * HH];

// ---------------- helpers ----------------
__device__ __forceinline__ uint32_t smem_u32(const void* p) {
    uint32_t a;
    asm("{ .reg .u64 t; cvta.to.shared.u64 t, %1; cvt.u32.u64 %0, t; }" : "=r"(a) : "l"(p));
    return a;
}
__device__ __forceinline__ uint32_t h2u(__half2 h) { return *(uint32_t*)&h; }

#define CPA(dst, src) \
    asm volatile("cp.async.cg.shared.global [%0], [%1], 16;" :: "r"(dst), "l"(src))
#define CP_COMMIT() asm volatile("cp.async.commit_group;" ::: "memory")
#define CP_WAIT1()  asm volatile("cp.async.wait_group 1;" ::: "memory")

#define LDSM4(r, addr) \
    asm volatile("ldmatrix.sync.aligned.m8n8.x4.shared.b16 {%0,%1,%2,%3}, [%4];" \
                 : "=r"((r)[0]), "=r"((r)[1]), "=r"((r)[2]), "=r"((r)[3]) : "r"(addr))

#define MMA(c, a, b) \
    asm volatile("mma.sync.aligned.m16n8k16.row.col.f32.f16.f16.f32 " \
                 "{%0,%1,%2,%3},{%4,%5,%6,%7},{%8,%9},{%0,%1,%2,%3};" \
                 : "+f"((c)[0]), "+f"((c)[1]), "+f"((c)[2]), "+f"((c)[3]) \
                 : "r"((a)[0]), "r"((a)[1]), "r"((a)[2]), "r"((a)[3]), \
                   "r"((b)[0]), "r"((b)[1]))

#define REDADD(ptr, val) \
    asm volatile("red.global.add.f32 [%0], %1;" :: "l"(ptr), "f"(val) : "memory")

// ---------------- kernel 0: zero output + reset counters ----------------
__global__ void k_zero(float* __restrict__ out) {
    if (blockIdx.x == 0 && threadIdx.x < EE) g_counts[threadIdx.x] = 0;
    size_t i = (size_t)blockIdx.x * blockDim.x + threadIdx.x;   // float4 index
    ((float4*)out)[i] = make_float4(0.f, 0.f, 0.f, 0.f);
}

// ---------------- kernel 1: x -> fp16 (rn) ----------------
__global__ void k_prep_x(const float* __restrict__ x) {
    size_t idx = (size_t)blockIdx.x * blockDim.x + threadIdx.x;  // float4 index
    float4 v = ((const float4*)x)[idx];
    __half2 h0 = __floats2half2_rn(v.x, v.y);
    __half2 h1 = __floats2half2_rn(v.z, v.w);
    ((uint2*)g_Ah)[idx] = make_uint2(h2u(h0), h2u(h1));
}

// ---------------- kernel 2: We [e][k][n] -> Bh/Bl fp16 [e][n][k], scaled ----------------
__global__ __launch_bounds__(512, 1)
void k_prep_B(const float* __restrict__ We) {
    const int e = blockIdx.z;
    const int k0 = blockIdx.y * 128 + (threadIdx.x >> 8) * 64;
    const int n0 = blockIdx.x * 64;
    __shared__ float t[2][64][65];
    float (*tt)[65] = t[threadIdx.x >> 8];
    const int tid = threadIdx.x & 255;
#pragma unroll
    for (int q = 0; q < 16; ++q) {
        int lin = q * 256 + tid;
        int kr = lin >> 6, nc = lin & 63;
        tt[kr][nc] = We[((size_t)e * HH + (k0 + kr)) * HH + n0 + nc];
    }
    __syncthreads();
#pragma unroll
    for (int q = 0; q < 8; ++q) {
        int lin = q * 256 + tid;
        int nr = lin >> 5, kc = (lin & 31) * 2;
        float a = tt[kc][nr] * BSCALE;
        float b = tt[kc + 1][nr] * BSCALE;
        __half2 h = __floats2half2_rn(a, b);
        float2 hf = __half22float2(h);
        __half2 l = __floats2half2_rn(a - hf.x, b - hf.y);
        size_t off = ((size_t)e * HH + (n0 + nr)) * HH + k0 + kc;
        *(uint32_t*)(g_Bh + off) = h2u(h);
        *(uint32_t*)(g_Bl + off) = h2u(l);
    }
}

// ---------------- kernel 3: gating (one warp per token; measured-good form) ------
__global__ void k_gate(const float* __restrict__ x,
                       const float* __restrict__ Wg,
                       const float* __restrict__ bg) {
    int gw = (blockIdx.x * blockDim.x + threadIdx.x) >> 5;
    int lane = threadIdx.x & 31;
    if (gw >= TT) return;
    const float* xr = x + (size_t)gw * HH;

    float acc[EE];
#pragma unroll
    for (int e = 0; e < EE; ++e) acc[e] = 0.0f;
    for (int h = lane; h < HH; h += 32) {
        float xv = xr[h];
        const float4* w4 = (const float4*)(Wg + (size_t)h * EE);
        float4 w0 = w4[0], w1 = w4[1];
        acc[0] += xv * w0.x; acc[1] += xv * w0.y;
        acc[2] += xv * w0.z; acc[3] += xv * w0.w;
        acc[4] += xv * w1.x; acc[5] += xv * w1.y;
        acc[6] += xv * w1.z; acc[7] += xv * w1.w;
    }
#pragma unroll
    for (int o = 16; o; o >>= 1)
#pragma unroll
        for (int e = 0; e < EE; ++e)
            acc[e] += __shfl_xor_sync(0xffffffffu, acc[e], o);

    if (lane == 0) {
        float m = -1e30f;
#pragma unroll
        for (int e = 0; e < EE; ++e) { acc[e] += bg[e]; m = fmaxf(m, acc[e]); }
        float sc[EE], s = 0.0f;
#pragma unroll
        for (int e = 0; e < EE; ++e) { sc[e] = expf(acc[e] - m); s += sc[e]; }
        float inv = 1.0f / s;
#pragma unroll
        for (int e = 0; e < EE; ++e) sc[e] *= inv;
        int e0 = 0;
#pragma unroll
        for (int e = 1; e < EE; ++e) if (sc[e] > sc[e0]) e0 = e;
        int e1 = (e0 == 0) ? 1 : 0;
#pragma unroll
        for (int e = 0; e < EE; ++e) if (e != e0 && sc[e] > sc[e1]) e1 = e;
        int t = gw;
        g_gate[2 * t + 0] = sc[e0];
        g_gate[2 * t + 1] = sc[e1];
        int p0 = atomicAdd(&g_counts[e0], 1);
        g_list[e0][p0] = 2 * t + 0;
        int p1 = atomicAdd(&g_counts[e1], 1);
        g_list[e1][p1] = 2 * t + 1;
    }
}

// ---------------- kernel 4: fp16 2-term grouped GEMM, 2 CTAs/SM ----------------
__global__ __launch_bounds__(256, 2)
void k_gemm_mma(const float* __restrict__ be, float* __restrict__ out) {
    const int e = blockIdx.z;
    const int count = g_counts[e];
    const int row0 = blockIdx.y * BM;
    if (row0 >= count) return;
    const int n0 = blockIdx.x * BN;

    extern __shared__ char smem_raw[];
    const uint32_t sb = smem_u32(smem_raw);
    const int tid = threadIdx.x;
    const int w = tid >> 5, l = tid & 31;

    // cp.async assignments: rows rA+32q, 16B chunk ch; 4 granules per matrix
    const int rA = tid >> 3;
    const int ch = tid & 7;
    const __half* srcA[4];
    const __half* srcBh[4];
    const __half* srcBl[4];
    uint32_t dstoff[4];
#pragma unroll
    for (int q = 0; q < 4; ++q) {
        int r = rA + 32 * q;
        int gr = row0 + r;
        int cl = (gr < count) ? gr : (count - 1);
        int slot = g_list[e][cl];
        srcA[q] = g_Ah + (size_t)(slot >> 1) * HH + ch * 8;
        size_t bbase = ((size_t)e * HH + n0 + r) * HH + ch * 8;
        srcBh[q] = g_Bh + bbase;
        srcBl[q] = g_Bl + bbase;
        dstoff[q] = (uint32_t)r * 128u + (uint32_t)((ch ^ (rA & 7)) << 4);
    }

    auto issue = [&](int s, int c) {
        const uint32_t base = sb + s * STAGE_BYTES;
        const int ke = c * BK;
#pragma unroll
        for (int q = 0; q < 4; ++q) CPA(base + dstoff[q], srcA[q] + ke);
#pragma unroll
        for (int q = 0; q < 4; ++q) CPA(base + MAT_BYTES + dstoff[q], srcBh[q] + ke);
#pragma unroll
        for (int q = 0; q < 4; ++q) CPA(base + 2 * MAT_BYTES + dstoff[q], srcBl[q] + ke);
    };

    // prologue: 2 stages in flight
    issue(0, 0); CP_COMMIT();
    issue(1, 1); CP_COMMIT();

    // per-warp tile: 64 rows x 32 cols
    const int m_base = (w & 1) * 64;
    const int n_base = (w >> 1) * 32;

    uint32_t rowA[4], rowB[2], xoA[4], xoB[4];
#pragma unroll
    for (int i = 0; i < 4; ++i) rowA[i] = (uint32_t)(m_base + 16 * i + (l & 15)) * 128u;
#pragma unroll
    for (int j2 = 0; j2 < 2; ++j2)
        rowB[j2] = (uint32_t)(n_base + 16 * j2 + (l & 7) + ((l >> 4) << 3)) * 128u;
#pragma unroll
    for (int ks = 0; ks < 4; ++ks) {
        xoA[ks] = (uint32_t)(((ks * 2 + (l >> 4)) ^ (l & 7)) << 4);
        xoB[ks] = (uint32_t)(((ks * 2 + ((l >> 3) & 1)) ^ (l & 7)) << 4);
    }

    float acc[4][4][4];
#pragma unroll
    for (int i = 0; i < 4; ++i)
#pragma unroll
        for (int j = 0; j < 4; ++j)
#pragma unroll
            for (int q = 0; q < 4; ++q) acc[i][j][q] = 0.0f;

    // single-buffered fragments (keeps regs <= 128 for occupancy 2)
    uint32_t fa[4][4], fb[2][4], fl[2][4];

    for (int c = 0; c < NCH; ++c) {
        CP_WAIT1();
        __syncthreads();

        const uint32_t Ah = sb + (c & 1) * STAGE_BYTES;
        const uint32_t Bh = Ah + MAT_BYTES;
        const uint32_t Bl = Ah + 2 * MAT_BYTES;

#pragma unroll
        for (int ks = 0; ks < 4; ++ks) {
#pragma unroll
            for (int i = 0; i < 4; ++i) LDSM4(fa[i], Ah + rowA[i] + xoA[ks]);
#pragma unroll
            for (int j2 = 0; j2 < 2; ++j2) {
                LDSM4(fb[j2], Bh + rowB[j2] + xoB[ks]);
                LDSM4(fl[j2], Bl + rowB[j2] + xoB[ks]);
            }
#pragma unroll
            for (int i = 0; i < 4; ++i) {
#pragma unroll
                for (int j = 0; j < 4; ++j) {
                    uint32_t* bh = &fb[j >> 1][(j & 1) * 2];
                    uint32_t* bl = &fl[j >> 1][(j & 1) * 2];
                    MMA(acc[i][j], fa[i], bh);
                    MMA(acc[i][j], fa[i], bl);
                }
            }
        }

        __syncthreads();
        if (c + 2 < NCH) issue((c + 2) & 1, c + 2);
        CP_COMMIT();
    }

    // epilogue: out[token] += gate * (acc/BSCALE + be)   (exactly 2 adds/elem -> deterministic)
    float2 bias[4];
#pragma unroll
    for (int j = 0; j < 4; ++j) {
        int col = n_base + 8 * j + 2 * (l & 3);
        bias[j] = *(const float2*)(be + (size_t)e * HH + n0 + col);
    }
#pragma unroll
    for (int i = 0; i < 4; ++i) {
#pragma unroll
        for (int half = 0; half < 2; ++half) {
            int r = m_base + 16 * i + (l >> 2) + 8 * half;
            int gr = row0 + r;
            if (gr < count) {
                int slot = g_list[e][gr];
                float gate = g_gate[slot];
                float gs = gate * INV_BSCALE;
                float* yr = out + (size_t)(slot >> 1) * HH + n0;
#pragma unroll
                for (int j = 0; j < 4; ++j) {
                    int col = n_base + 8 * j + 2 * (l & 3);
                    float vx = gs * acc[i][j][half * 2 + 0] + gate * bias[j].x;
                    float vy = gs * acc[i][j][half * 2 + 1] + gate * bias[j].y;
                    REDADD(yr + col, vx);
                    REDADD(yr + col + 1, vy);
                }
            }
        }
    }
}

// ---------------- launch ----------------
extern "C" void kernel_launch(void* const* d_in, const int* in_sizes, int n_in,
                              void* d_out, int out_size) {
    const float* x  = (const float*)d_in[0];
    const float* Wg = (const float*)d_in[1];
    const float* bg = (const float*)d_in[2];
    const float* We = (const float*)d_in[3];
    const float* be = (const float*)d_in[4];
    float* out = (float*)d_out;

    cudaFuncSetAttribute(k_gemm_mma, cudaFuncAttributeMaxDynamicSharedMemorySize, SMEM_NEED);

    k_zero<<<(TT * (HH / 4)) / 256, 256>>>(out);
    k_prep_x<<<(TT * HH / 4) / 256, 256>>>(x);
    k_prep_B<<<dim3(HH / 64, HH / 128, EE), 512>>>(We);
    k_gate<<<TT / 8, 256>>>(x, Wg, bg);
    k_gemm_mma<<<dim3(HH / BN, TT / BM, EE), 256, SMEM_NEED>>>(be, out);
}

// round 14
// speedup vs baseline: 6.0829x; 1.4811x over previous
#include <cuda_runtime.h>
#include <cuda_fp16.h>
#include <cstdint>

// Problem constants
#define TT 8192
#define HH 2048
#define EE 8

// GEMM config
#define BM 128
#define BN 128
#define BK 64
#define NCH (HH / BK)          // 32 k-chunks
#define STG 3
#define MAT_BYTES 16384        // 128 rows x 128B (64 fp16)
#define STAGE_BYTES (2 * MAT_BYTES)       // Ah, Bh  (32KB)
#define SMEM_NEED (STG * STAGE_BYTES)     // 98304 -> 2 CTAs/SM
#define BSCALE 4096.0f
#define INV_BSCALE (1.0f / 4096.0f)

// ---------------- static scratch ----------------
__device__ int    g_counts[EE];
__device__ int    g_list[EE][TT];
__device__ float  g_gate[2 * TT];
__device__ __half g_Ah[(size_t)TT * HH];
__device__ __half g_Bh[(size_t)EE * HH * HH];   // [e][n][k], scaled by 4096

// ---------------- helpers ----------------
__device__ __forceinline__ uint32_t smem_u32(const void* p) {
    uint32_t a;
    asm("{ .reg .u64 t; cvta.to.shared.u64 t, %1; cvt.u32.u64 %0, t; }" : "=r"(a) : "l"(p));
    return a;
}
__device__ __forceinline__ uint32_t h2u(__half2 h) { return *(uint32_t*)&h; }

#define CPA(dst, src) \
    asm volatile("cp.async.cg.shared.global [%0], [%1], 16;" :: "r"(dst), "l"(src))
#define CP_COMMIT() asm volatile("cp.async.commit_group;" ::: "memory")
#define CP_WAIT1()  asm volatile("cp.async.wait_group 1;" ::: "memory")

#define LDSM4(r, addr) \
    asm volatile("ldmatrix.sync.aligned.m8n8.x4.shared.b16 {%0,%1,%2,%3}, [%4];" \
                 : "=r"((r)[0]), "=r"((r)[1]), "=r"((r)[2]), "=r"((r)[3]) : "r"(addr))

#define MMA(c, a, b) \
    asm volatile("mma.sync.aligned.m16n8k16.row.col.f32.f16.f16.f32 " \
                 "{%0,%1,%2,%3},{%4,%5,%6,%7},{%8,%9},{%0,%1,%2,%3};" \
                 : "+f"((c)[0]), "+f"((c)[1]), "+f"((c)[2]), "+f"((c)[3]) \
                 : "r"((a)[0]), "r"((a)[1]), "r"((a)[2]), "r"((a)[3]), \
                   "r"((b)[0]), "r"((b)[1]))

#define REDADD(ptr, val) \
    asm volatile("red.global.add.f32 [%0], %1;" :: "l"(ptr), "f"(val) : "memory")

// ---------------- kernel 0: zero output + reset counters ----------------
__global__ void k_zero(float* __restrict__ out) {
    if (blockIdx.x == 0 && threadIdx.x < EE) g_counts[threadIdx.x] = 0;
    size_t i = (size_t)blockIdx.x * blockDim.x + threadIdx.x;   // float4 index
    ((float4*)out)[i] = make_float4(0.f, 0.f, 0.f, 0.f);
}

// ---------------- kernel 1: x -> fp16 (rn) ----------------
__global__ void k_prep_x(const float* __restrict__ x) {
    size_t idx = (size_t)blockIdx.x * blockDim.x + threadIdx.x;  // float4 index
    float4 v = ((const float4*)x)[idx];
    __half2 h0 = __floats2half2_rn(v.x, v.y);
    __half2 h1 = __floats2half2_rn(v.z, v.w);
    ((uint2*)g_Ah)[idx] = make_uint2(h2u(h0), h2u(h1));
}

// ---------------- kernel 2: We [e][k][n] -> Bh fp16 [e][n][k], scaled ----------------
__global__ __launch_bounds__(512, 1)
void k_prep_B(const float* __restrict__ We) {
    const int e = blockIdx.z;
    const int k0 = blockIdx.y * 128 + (threadIdx.x >> 8) * 64;
    const int n0 = blockIdx.x * 64;
    __shared__ float t[2][64][65];
    float (*tt)[65] = t[threadIdx.x >> 8];
    const int tid = threadIdx.x & 255;
#pragma unroll
    for (int q = 0; q < 16; ++q) {
        int lin = q * 256 + tid;
        int kr = lin >> 6, nc = lin & 63;
        tt[kr][nc] = We[((size_t)e * HH + (k0 + kr)) * HH + n0 + nc];
    }
    __syncthreads();
#pragma unroll
    for (int q = 0; q < 8; ++q) {
        int lin = q * 256 + tid;
        int nr = lin >> 5, kc = (lin & 31) * 2;
        float a = tt[kc][nr] * BSCALE;
        float b = tt[kc + 1][nr] * BSCALE;
        __half2 h = __floats2half2_rn(a, b);
        size_t off = ((size_t)e * HH + (n0 + nr)) * HH + k0 + kc;
        *(uint32_t*)(g_Bh + off) = h2u(h);
    }
}

// ---------------- kernel 3: gating (one warp per token; measured-good form) ------
__global__ void k_gate(const float* __restrict__ x,
                       const float* __restrict__ Wg,
                       const float* __restrict__ bg) {
    int gw = (blockIdx.x * blockDim.x + threadIdx.x) >> 5;
    int lane = threadIdx.x & 31;
    if (gw >= TT) return;
    const float* xr = x + (size_t)gw * HH;

    float acc[EE];
#pragma unroll
    for (int e = 0; e < EE; ++e) acc[e] = 0.0f;
    for (int h = lane; h < HH; h += 32) {
        float xv = xr[h];
        const float4* w4 = (const float4*)(Wg + (size_t)h * EE);
        float4 w0 = w4[0], w1 = w4[1];
        acc[0] += xv * w0.x; acc[1] += xv * w0.y;
        acc[2] += xv * w0.z; acc[3] += xv * w0.w;
        acc[4] += xv * w1.x; acc[5] += xv * w1.y;
        acc[6] += xv * w1.z; acc[7] += xv * w1.w;
    }
#pragma unroll
    for (int o = 16; o; o >>= 1)
#pragma unroll
        for (int e = 0; e < EE; ++e)
            acc[e] += __shfl_xor_sync(0xffffffffu, acc[e], o);

    if (lane == 0) {
        float m = -1e30f;
#pragma unroll
        for (int e = 0; e < EE; ++e) { acc[e] += bg[e]; m = fmaxf(m, acc[e]); }
        float sc[EE], s = 0.0f;
#pragma unroll
        for (int e = 0; e < EE; ++e) { sc[e] = expf(acc[e] - m); s += sc[e]; }
        float inv = 1.0f / s;
#pragma unroll
        for (int e = 0; e < EE; ++e) sc[e] *= inv;
        int e0 = 0;
#pragma unroll
        for (int e = 1; e < EE; ++e) if (sc[e] > sc[e0]) e0 = e;
        int e1 = (e0 == 0) ? 1 : 0;
#pragma unroll
        for (int e = 0; e < EE; ++e) if (e != e0 && sc[e] > sc[e1]) e1 = e;
        int t = gw;
        g_gate[2 * t + 0] = sc[e0];
        g_gate[2 * t + 1] = sc[e1];
        int p0 = atomicAdd(&g_counts[e0], 1);
        g_list[e0][p0] = 2 * t + 0;
        int p1 = atomicAdd(&g_counts[e1], 1);
        g_list[e1][p1] = 2 * t + 1;
    }
}

// ---------------- kernel 4: fp16 grouped GEMM, 3-stage, 2 CTAs/SM ----------------
__global__ __launch_bounds__(256, 2)
void k_gemm_mma(const float* __restrict__ be, float* __restrict__ out) {
    const int e = blockIdx.z;
    const int count = g_counts[e];
    const int row0 = blockIdx.y * BM;
    if (row0 >= count) return;
    const int n0 = blockIdx.x * BN;

    extern __shared__ char smem_raw[];
    const uint32_t sb = smem_u32(smem_raw);
    const int tid = threadIdx.x;
    const int w = tid >> 5, l = tid & 31;

    // cp.async assignments: rows rA+32q, 16B chunk ch; 4 granules per matrix
    const int rA = tid >> 3;
    const int ch = tid & 7;
    const __half* srcA[4];
    const __half* srcBh[4];
    uint32_t dstoff[4];
#pragma unroll
    for (int q = 0; q < 4; ++q) {
        int r = rA + 32 * q;
        int gr = row0 + r;
        int cl = (gr < count) ? gr : (count - 1);
        int slot = g_list[e][cl];
        srcA[q] = g_Ah + (size_t)(slot >> 1) * HH + ch * 8;
        srcBh[q] = g_Bh + ((size_t)e * HH + n0 + r) * HH + ch * 8;
        dstoff[q] = (uint32_t)r * 128u + (uint32_t)((ch ^ (rA & 7)) << 4);
    }

    auto issue = [&](int s, int c) {
        const uint32_t base = sb + s * STAGE_BYTES;
        const int ke = c * BK;
#pragma unroll
        for (int q = 0; q < 4; ++q) CPA(base + dstoff[q], srcA[q] + ke);
#pragma unroll
        for (int q = 0; q < 4; ++q) CPA(base + MAT_BYTES + dstoff[q], srcBh[q] + ke);
    };

    // prologue: 2 stages in flight
    issue(0, 0); CP_COMMIT();
    issue(1, 1); CP_COMMIT();

    // per-warp tile: 64 rows x 32 cols
    const int m_base = (w & 1) * 64;
    const int n_base = (w >> 1) * 32;

    uint32_t rowA[4], rowB[2], xoA[4], xoB[4];
#pragma unroll
    for (int i = 0; i < 4; ++i) rowA[i] = (uint32_t)(m_base + 16 * i + (l & 15)) * 128u;
#pragma unroll
    for (int j2 = 0; j2 < 2; ++j2)
        rowB[j2] = (uint32_t)(n_base + 16 * j2 + (l & 7) + ((l >> 4) << 3)) * 128u;
#pragma unroll
    for (int ks = 0; ks < 4; ++ks) {
        xoA[ks] = (uint32_t)(((ks * 2 + (l >> 4)) ^ (l & 7)) << 4);
        xoB[ks] = (uint32_t)(((ks * 2 + ((l >> 3) & 1)) ^ (l & 7)) << 4);
    }

    float acc[4][4][4];
#pragma unroll
    for (int i = 0; i < 4; ++i)
#pragma unroll
        for (int j = 0; j < 4; ++j)
#pragma unroll
            for (int q = 0; q < 4; ++q) acc[i][j][q] = 0.0f;

    uint32_t fa[4][4], fb[2][4];

    for (int c = 0; c < NCH; ++c) {
        CP_WAIT1();
        __syncthreads();
        // stage (c+2)%3 was consumed in iteration c-1 (all threads past it) -> safe to refill
        if (c + 2 < NCH) issue((c + 2) % STG, c + 2);
        CP_COMMIT();

        const uint32_t Ah = sb + (c % STG) * STAGE_BYTES;
        const uint32_t Bh = Ah + MAT_BYTES;

#pragma unroll
        for (int ks = 0; ks < 4; ++ks) {
#pragma unroll
            for (int i = 0; i < 4; ++i) LDSM4(fa[i], Ah + rowA[i] + xoA[ks]);
#pragma unroll
            for (int j2 = 0; j2 < 2; ++j2) LDSM4(fb[j2], Bh + rowB[j2] + xoB[ks]);
#pragma unroll
            for (int i = 0; i < 4; ++i) {
#pragma unroll
                for (int j = 0; j < 4; ++j) {
                    MMA(acc[i][j], fa[i], (&fb[j >> 1][(j & 1) * 2]));
                }
            }
        }
    }

    // epilogue: out[token] += gate * (acc/BSCALE + be)   (exactly 2 adds/elem -> deterministic)
    float2 bias[4];
#pragma unroll
    for (int j = 0; j < 4; ++j) {
        int col = n_base + 8 * j + 2 * (l & 3);
        bias[j] = *(const float2*)(be + (size_t)e * HH + n0 + col);
    }
#pragma unroll
    for (int i = 0; i < 4; ++i) {
#pragma unroll
        for (int half = 0; half < 2; ++half) {
            int r = m_base + 16 * i + (l >> 2) + 8 * half;
            int gr = row0 + r;
            if (gr < count) {
                int slot = g_list[e][gr];
                float gate = g_gate[slot];
                float gs = gate * INV_BSCALE;
                float* yr = out + (size_t)(slot >> 1) * HH + n0;
#pragma unroll
                for (int j = 0; j < 4; ++j) {
                    int col = n_base + 8 * j + 2 * (l & 3);
                    float vx = gs * acc[i][j][half * 2 + 0] + gate * bias[j].x;
                    float vy = gs * acc[i][j][half * 2 + 1] + gate * bias[j].y;
                    REDADD(yr + col, vx);
                    REDADD(yr + col + 1, vy);
                }
            }
        }
    }
}

// ---------------- launch ----------------
extern "C" void kernel_launch(void* const* d_in, const int* in_sizes, int n_in,
                              void* d_out, int out_size) {
    const float* x  = (const float*)d_in[0];
    const float* Wg = (const float*)d_in[1];
    const float* bg = (const float*)d_in[2];
    const float* We = (const float*)d_in[3];
    const float* be = (const float*)d_in[4];
    float* out = (float*)d_out;

    cudaFuncSetAttribute(k_gemm_mma, cudaFuncAttributeMaxDynamicSharedMemorySize, SMEM_NEED);

    k_zero<<<(TT * (HH / 4)) / 256, 256>>>(out);
    k_prep_x<<<(TT * HH / 4) / 256, 256>>>(x);
    k_prep_B<<<dim3(HH / 64, HH / 128, EE), 512>>>(We);
    k_gate<<<TT / 8, 256>>>(x, Wg, bg);
    k_gemm_mma<<<dim3(HH / BN, TT / BM, EE), 256, SMEM_NEED>>>(be, out);
}